// round 7
// baseline (speedup 1.0000x reference)
#include <cuda_runtime.h>
#include <cuda_bf16.h>

// EdgeToVertex: tril(x) * 257x257 "plus" kernel, stride (256,1), SAME
// -> out [512, 1, 256, 1].
//
// out[b,w] = colsum(w)                 colsum(w) = sum_{r=w..255} x[b,r,w]
//          + S                          S = sum_{c=0..128} x[b,128,c]
//          - 2*x[b,128,w]     (w<=128)
//          - prefix128(w-129) (w>=129)
//
// R7: one CTA per image (512 x 1024 threads), direct store. Thread t owns
// float4 column group c4 = t&63 over rows 16*(t>>6)..+15: 16 predicated
// LDG.128 (skip above-diagonal vectors, register-mask the straddler). All 16
// row-group partials reduce in smem per column, the row-128 prefix-scan
// correction is done with a 2-barrier shfl warp-scan, and thread w<256
// stores out[b,w]. No atomics, no zero-init kernel, single launch.

#define NN 256
#define NB 512

__global__ __launch_bounds__(1024, 2) void etv_kernel(const float* __restrict__ x,
                                                      float* __restrict__ out) {
    const int b  = blockIdx.x;
    const int t  = threadIdx.x;
    const int c4 = t & 63;                 // column group (cols 4c4..4c4+3)
    const int g  = t >> 6;                 // row group 0..15 (16 rows each)
    const int r0 = g * 16;
    const int cbase = c4 * 4;
    const float* __restrict__ X = x + (size_t)b * (NN * NN);
    const float* p = X + r0 * NN + cbase;

    float4 acc = make_float4(0.f, 0.f, 0.f, 0.f);
    #pragma unroll
    for (int i = 0; i < 16; ++i) {
        const int r = r0 + i;
        if (cbase <= r) {                  // at least one component in tril
            float4 v = *reinterpret_cast<const float4*>(p + i * NN);
            const int d = r - cbase;       // 0..3 => straddles the diagonal
            if (d < 3) {
                if (d < 1) v.y = 0.f;
                if (d < 2) v.z = 0.f;
                v.w = 0.f;
            }
            acc.x += v.x; acc.y += v.y; acc.z += v.z; acc.w += v.w;
        }
    }

    // Per-column reduction across the 16 row groups.
    __shared__ float4 part[16][64];        // float layout: [j][w] contiguous in w
    part[g][c4] = acc;

    // Row-128 value (cols 0..128 survive tril); re-read is an L1/L2 hit for
    // the CTA that loaded row 128 (this CTA - it owns the whole image).
    const int  w   = t;                    // output column for t < 256
    float myv = 0.f;
    if (t < 256) myv = (w <= 128) ? X[128 * NN + w] : 0.f;
    __syncthreads();

    float colsum = 0.f;
    if (t < 256) {
        const float* pf = reinterpret_cast<const float*>(part);
        #pragma unroll
        for (int j = 0; j < 16; ++j)
            colsum += pf[j * 256 + w];     // consecutive addresses per thread
    }

    // Inclusive prefix scan of row 128 over 256 columns: shfl within warps
    // 0..7, then cross-warp offsets (2 barriers total).
    __shared__ float wsum[8];
    __shared__ float sdata[NN];
    if (t < 256) {
        const int lane = t & 31;
        const int wrp  = t >> 5;           // 0..7
        float v = myv;
        #pragma unroll
        for (int off = 1; off < 32; off <<= 1) {
            float n = __shfl_up_sync(0xffffffff, v, off);
            if (lane >= off) v += n;
        }
        if (lane == 31) wsum[wrp] = v;
    }
    __syncthreads();
    if (t < 256) {
        const int wrp = t >> 5;
        float base = 0.f;
        #pragma unroll
        for (int j = 0; j < 7; ++j)
            if (j < wrp) base += wsum[j];
        float v = myv;
        const int lane = t & 31;
        #pragma unroll
        for (int off = 1; off < 32; off <<= 1) {
            float n = __shfl_up_sync(0xffffffff, v, off);
            if (lane >= off) v += n;
        }
        sdata[w] = v + base;               // inclusive prefix over cols 0..w
    }
    __syncthreads();

    if (t < 256) {
        const float S = sdata[128];
        const float res = (w <= 128) ? (colsum + S - 2.0f * myv)
                                     : (colsum + S - sdata[w - 129]);
        out[b * NN + w] = res;
    }
}

extern "C" void kernel_launch(void* const* d_in, const int* in_sizes, int n_in,
                              void* d_out, int out_size) {
    const float* x = (const float*)d_in[0];
    if (n_in > 1 && in_sizes[0] != NB * NN * NN) {
        for (int i = 0; i < n_in; ++i) {
            if (in_sizes[i] == NB * NN * NN) { x = (const float*)d_in[i]; break; }
        }
    }
    float* out = (float*)d_out;
    etv_kernel<<<NB, 1024>>>(x, out);
}